// round 15
// baseline (speedup 1.0000x reference)
#include <cuda_runtime.h>
#include <math.h>
#include <cstdint>

#define B_DIM 4
#define L_DIM 4096
#define D_DIM 1024
#define NFFT 8192

// ---------------- scratch (static device globals; no allocation) -----------
__device__ float  g_uT[(size_t)B_DIM * D_DIM * L_DIM];   // [B, D, L]
__device__ float  g_vT[(size_t)B_DIM * D_DIM * L_DIM];   // [B, D, L] (reused for yT)
__device__ float  g_xr[(size_t)B_DIM * L_DIM * D_DIM];   // x rounded to tf32, K pair-permuted
__device__ float  g_Wt[(size_t)3 * D_DIM * D_DIM];       // Wu^T, Wv^T (permuted), Wo^T (plain)
__device__ float2 g_Hf[(size_t)D_DIM * NFFT];            // [D][k<=4096] used
__device__ float2 g_tw[NFFT];                            // exp(-2pi i k / 8192)

// ======================= portable PTX helpers ===============================
__device__ __forceinline__ uint32_t smem_u32(const void* p) {
    uint32_t a;
    asm("{ .reg .u64 t; cvta.to.shared.u64 t, %1; cvt.u32.u64 %0, t; }" : "=r"(a) : "l"(p));
    return a;
}
__device__ __forceinline__ uint32_t f2tf(float f) {
    uint32_t u; asm("cvt.rna.tf32.f32 %0, %1;" : "=r"(u) : "f"(f)); return u;
}
__device__ __forceinline__ void cp_async16(uint32_t saddr, const void* g) {
    asm volatile("cp.async.cg.shared.global [%0], [%1], 16;" :: "r"(saddr), "l"(g));
}
#define CP_COMMIT() asm volatile("cp.async.commit_group;" ::: "memory")
#define CP_WAIT1()  asm volatile("cp.async.wait_group 1;" ::: "memory")
#define CP_WAIT0()  asm volatile("cp.async.wait_group 0;" ::: "memory")

__device__ __forceinline__ void mma_tf32(float* c,
    uint32_t a0, uint32_t a1, uint32_t a2, uint32_t a3, uint32_t b0, uint32_t b1) {
    asm volatile(
        "mma.sync.aligned.m16n8k8.row.col.f32.tf32.tf32.f32 "
        "{%0,%1,%2,%3}, {%4,%5,%6,%7}, {%8,%9}, {%0,%1,%2,%3};"
        : "+f"(c[0]), "+f"(c[1]), "+f"(c[2]), "+f"(c[3])
        : "r"(a0), "r"(a1), "r"(a2), "r"(a3), "r"(b0), "r"(b1));
}
__device__ __forceinline__ uint32_t u32f(float f) { return __float_as_uint(f); }

// ======================= tf32 mma.sync GEMMs ================================
// Round-13 config: 128x128 tile, 8 warps 4(m)x2(n), warp tile 32x64,
// 3-stage pipeline, one barrier/stage, register-rotated stage offsets,
// unpadded 32-float rows + XOR chunk swizzle.
// gemm_uv additionally uses K pair-permuted operands -> LDS.64 fragment loads.
#define AROW2 136
#define UV_STAGE_B   32768
#define UV_SMEM_B    98304
#define OUT_STAGE_B  33792
#define OUT_SMEM_B   101376

// ---- GEMM1 fused u+v: C[i=e][j=m]; z = bx&1 picks (Wu,bu,U) / (Wv,bv,V) ----
__global__ void __launch_bounds__(256, 2) gemm_uv(
    const float* __restrict__ Wt, const float* __restrict__ X,
    const float* __restrict__ bu, const float* __restrict__ bv,
    float* __restrict__ U, float* __restrict__ V)
{
    extern __shared__ float sm[];
    const uint32_t smb = smem_u32(sm);

    const int z  = blockIdx.x & 1;
    const int j0 = (blockIdx.x >> 1) * 128;
    const int i0 = blockIdx.y * 128;
    const float* Ag   = Wt + (size_t)z * 1024 * 1024;
    const float* bias = z ? bv : bu;
    float*       Cg   = z ? V : U;

    const int tid  = threadIdx.x;
    const int lane = tid & 31;
    const int wid  = tid >> 5;
    const int g    = lane >> 2;
    const int fi   = lane & 3;
    const int wm   = (wid & 3) * 32;
    const int wn   = (wid >> 2) * 64;

    const int q     = tid & 7;
    const int rbase = tid >> 3;
    const int qsw   = ((q ^ (rbase & 7)) << 2);

    const float* ag = Ag + (size_t)(i0 + rbase) * 1024 + q * 4;
    const float* bg = X  + (size_t)(j0 + rbase) * 1024 + q * 4;
    const uint32_t soff = (uint32_t)((rbase * 32 + qsw) << 2);

    auto load_stage = [&](int s, uint32_t stoff) {
        const int k0 = s * 32;
        const uint32_t sa  = smb + stoff + soff;
        const uint32_t sbx = smb + stoff + 16384u + soff;
        #pragma unroll
        for (int it = 0; it < 4; ++it) {
            cp_async16(sa  + it * 4096u, ag + (size_t)it * 32 * 1024 + k0);
            cp_async16(sbx + it * 4096u, bg + (size_t)it * 32 * 1024 + k0);
        }
    };

    float c[2][8][4];
    #pragma unroll
    for (int mt = 0; mt < 2; ++mt)
        #pragma unroll
        for (int nt = 0; nt < 8; ++nt)
            #pragma unroll
            for (int r = 0; r < 4; ++r) c[mt][nt][r] = 0.f;

    uint32_t st_cur = 0, st_nxt = UV_STAGE_B, st_spr = 2 * UV_STAGE_B;
    load_stage(0, st_cur); CP_COMMIT();
    load_stage(1, st_nxt); CP_COMMIT();

    // float2 offset (in float2 units) within a 16-float2 row, per kk:
    // chunk c = 2kk + (fi>>1), swizzled c^g, then (fi&1) selects half-chunk.
    int cfr[4];
    #pragma unroll
    for (int kk = 0; kk < 4; ++kk)
        cfr[kk] = ((((2 * kk + (fi >> 1)) ^ g) << 1) + (fi & 1));

    #pragma unroll 1
    for (int s = 0; s < 32; ++s) {
        if (s < 31) { CP_WAIT1(); } else { CP_WAIT0(); }
        __syncthreads();
        if (s + 2 < 32) { load_stage(s + 2, st_spr); CP_COMMIT(); }
        const float2* A2 = reinterpret_cast<const float2*>(sm + (st_cur >> 2));
        const float2* B2 = A2 + 2048;                 // +16384 bytes
        #pragma unroll
        for (int kk = 0; kk < 4; ++kk) {
            const int cc = cfr[kk];
            uint32_t a[2][4];
            #pragma unroll
            for (int mt = 0; mt < 2; ++mt) {
                const int r = wm + mt * 16;
                float2 av0 = A2[(r + g    ) * 16 + cc];   // logical (fi, fi+4)
                float2 av1 = A2[(r + g + 8) * 16 + cc];
                a[mt][0] = u32f(av0.x);
                a[mt][1] = u32f(av1.x);
                a[mt][2] = u32f(av0.y);
                a[mt][3] = u32f(av1.y);
            }
            #pragma unroll
            for (int nt = 0; nt < 8; ++nt) {
                const int n = wn + nt * 8;
                float2 bv = B2[(n + g) * 16 + cc];        // logical (fi, fi+4)
                mma_tf32(c[0][nt], a[0][0], a[0][1], a[0][2], a[0][3],
                         u32f(bv.x), u32f(bv.y));
                mma_tf32(c[1][nt], a[1][0], a[1][1], a[1][2], a[1][3],
                         u32f(bv.x), u32f(bv.y));
            }
        }
        const uint32_t t = st_cur; st_cur = st_nxt; st_nxt = st_spr; st_spr = t;
    }

    float* Cs = sm;
    __syncthreads();
    #pragma unroll
    for (int mt = 0; mt < 2; ++mt) {
        #pragma unroll
        for (int nt = 0; nt < 8; ++nt) {
            const int r  = wm + mt * 16 + g;
            const int cc = wn + nt * 8 + 2 * fi;
            *reinterpret_cast<float2*>(&Cs[(size_t)r * 136 + cc]) =
                make_float2(c[mt][nt][0], c[mt][nt][1]);
            *reinterpret_cast<float2*>(&Cs[(size_t)(r + 8) * 136 + cc]) =
                make_float2(c[mt][nt][2], c[mt][nt][3]);
        }
    }
    __syncthreads();

    #pragma unroll 1
    for (int p = 0; p < 16; ++p) {
        const int idx = p * 256 + tid;
        const int row = idx >> 5;
        const int qq  = idx & 31;
        float4 v = *reinterpret_cast<const float4*>(&Cs[(size_t)row * 136 + qq * 4]);
        const float be = __ldg(bias + i0 + row);
        v.x += be; v.y += be; v.z += be; v.w += be;
        const size_t base = ((size_t)(j0 >> 12) << 22) +
                            (size_t)(i0 + row) * 4096 + (j0 & 4095);
        *reinterpret_cast<float4*>(Cg + base + qq * 4) = v;
    }
}

// ---- GEMM2 (round-13 version, unpermuted): C[i=m][j=e] ---------------------
__global__ void __launch_bounds__(256, 2) gemm_out(
    const float* __restrict__ Ag, const float* __restrict__ Bg,
    const float* __restrict__ bias, float* __restrict__ Cg)
{
    extern __shared__ float sm[];
    const uint32_t smb = smem_u32(sm);

    const int tid  = threadIdx.x;
    const int lane = tid & 31;
    const int wid  = tid >> 5;
    const int g    = lane >> 2;
    const int fi   = lane & 3;
    const int wm   = (wid & 3) * 32;
    const int wn   = (wid >> 2) * 64;
    const int i0   = blockIdx.y * 128;
    const int j0   = blockIdx.x * 128;

    const int q     = tid & 7;
    const int rbase = tid >> 3;
    const int qsw   = ((q ^ (rbase & 7)) << 2);

    const float* bg = Bg + (size_t)(j0 + rbase) * 1024 + q * 4;
    const uint32_t soffB = (uint32_t)((rbase * 32 + qsw) << 2);

    const int bb = i0 >> 12, l0 = i0 & 4095;
    const int arow = tid >> 5;
    const int aq   = tid & 31;
    const float* ag = Ag + ((size_t)bb * 1024) * 4096 + l0 + aq * 4;
    const uint32_t soffA = (uint32_t)((arow * AROW2 + aq * 4) << 2);

    auto load_stage = [&](int s, uint32_t stoff) {
        const int k0 = s * 32;
        const uint32_t sa  = smb + stoff + soffA;
        const uint32_t sbx = smb + stoff + 17408u + soffB;
        #pragma unroll
        for (int it = 0; it < 4; ++it)
            cp_async16(sa + it * (8 * AROW2 * 4),
                       ag + (size_t)(k0 + arow + it * 8) * 4096);
        #pragma unroll
        for (int it = 0; it < 4; ++it)
            cp_async16(sbx + it * 4096u, bg + (size_t)it * 32 * 1024 + k0);
    };

    float c[2][8][4];
    #pragma unroll
    for (int mt = 0; mt < 2; ++mt)
        #pragma unroll
        for (int nt = 0; nt < 8; ++nt)
            #pragma unroll
            for (int r = 0; r < 4; ++r) c[mt][nt][r] = 0.f;

    uint32_t st_cur = 0, st_nxt = OUT_STAGE_B, st_spr = 2 * OUT_STAGE_B;
    load_stage(0, st_cur); CP_COMMIT();
    load_stage(1, st_nxt); CP_COMMIT();

    int cb0[4], cb1[4];
    #pragma unroll
    for (int kk = 0; kk < 4; ++kk) {
        cb0[kk] = (((2 * kk    ) ^ g) << 2) + fi;
        cb1[kk] = (((2 * kk + 1) ^ g) << 2) + fi;
    }

    #pragma unroll 1
    for (int s = 0; s < 32; ++s) {
        if (s < 31) { CP_WAIT1(); } else { CP_WAIT0(); }
        __syncthreads();
        if (s + 2 < 32) { load_stage(s + 2, st_spr); CP_COMMIT(); }
        const float* A = sm + (st_cur >> 2);
        const float* B = A + 4352;
        #pragma unroll
        for (int kk = 0; kk < 4; ++kk) {
            const int k0 = kk * 8;
            uint32_t a[2][4];
            #pragma unroll
            for (int mt = 0; mt < 2; ++mt) {
                const int r = wm + mt * 16;
                a[mt][0] = u32f(A[(k0 + fi    ) * AROW2 + r + g    ]);
                a[mt][1] = u32f(A[(k0 + fi    ) * AROW2 + r + g + 8]);
                a[mt][2] = u32f(A[(k0 + fi + 4) * AROW2 + r + g    ]);
                a[mt][3] = u32f(A[(k0 + fi + 4) * AROW2 + r + g + 8]);
            }
            #pragma unroll
            for (int nt = 0; nt < 8; ++nt) {
                const int n = wn + nt * 8;
                uint32_t b0 = u32f(B[(n + g) * 32 + cb0[kk]]);
                uint32_t b1 = u32f(B[(n + g) * 32 + cb1[kk]]);
                mma_tf32(c[0][nt], a[0][0], a[0][1], a[0][2], a[0][3], b0, b1);
                mma_tf32(c[1][nt], a[1][0], a[1][1], a[1][2], a[1][3], b0, b1);
            }
        }
        const uint32_t t = st_cur; st_cur = st_nxt; st_nxt = st_spr; st_spr = t;
    }

    float* Cs = sm;
    __syncthreads();
    #pragma unroll
    for (int mt = 0; mt < 2; ++mt) {
        #pragma unroll
        for (int nt = 0; nt < 8; ++nt) {
            const int r  = wm + mt * 16 + g;
            const int cc = wn + nt * 8 + 2 * fi;
            *reinterpret_cast<float2*>(&Cs[(size_t)r * 136 + cc]) =
                make_float2(c[mt][nt][0], c[mt][nt][1]);
            *reinterpret_cast<float2*>(&Cs[(size_t)(r + 8) * 136 + cc]) =
                make_float2(c[mt][nt][2], c[mt][nt][3]);
        }
    }
    __syncthreads();

    #pragma unroll 1
    for (int p = 0; p < 16; ++p) {
        const int idx = p * 256 + tid;
        const int row = idx >> 5;
        const int qq  = idx & 31;
        float4 v = *reinterpret_cast<const float4*>(&Cs[(size_t)row * 136 + qq * 4]);
        float4 bz = *reinterpret_cast<const float4*>(bias + j0 + qq * 4);
        v.x += bz.x; v.y += bz.y; v.z += bz.z; v.w += bz.w;
        *reinterpret_cast<float4*>(Cg + (size_t)(i0 + row) * 1024 + j0 + qq * 4) = v;
    }
}

// ---------------- fused 3x weight transpose + tf32 round (+perm z<2) --------
// K pair-permutation: logical col j -> physical (j&~7) + (j&3)*2 + ((j>>2)&1)
__global__ void transpose3_k(const float* __restrict__ W0, const float* __restrict__ W1,
                             const float* __restrict__ W2, float* __restrict__ out) {
    __shared__ float t[32][33];
    const int zz = blockIdx.z;
    const float* in = (zz == 0) ? W0 : ((zz == 1) ? W1 : W2);
    float* o = out + (size_t)zz * 1024 * 1024;
    const int r0 = blockIdx.y * 32;
    const int c0 = blockIdx.x * 32;
    #pragma unroll
    for (int i = threadIdx.y; i < 32; i += 8)
        t[i][threadIdx.x] = in[(size_t)(r0 + i) * 1024 + c0 + threadIdx.x];
    __syncthreads();
    #pragma unroll
    for (int i = threadIdx.y; i < 32; i += 8) {
        int d = r0 + threadIdx.x;                      // output column (K dim)
        if (zz < 2) d = (d & ~7) + ((d & 3) << 1) + ((d >> 2) & 1);
        o[(size_t)(c0 + i) * 1024 + d] = __uint_as_float(f2tf(t[threadIdx.x][i]));
    }
}

// ---------------- round x to tf32 with K pair-permutation -------------------
// Each thread handles one 8-float group: phys order [0,4,1,5,2,6,3,7].
__global__ void round_tf32_k(const float* __restrict__ in, float* __restrict__ out) {
    const size_t base = ((size_t)blockIdx.x * 256 + threadIdx.x) * 8;
    float4 lo = *reinterpret_cast<const float4*>(in + base);
    float4 hi = *reinterpret_cast<const float4*>(in + base + 4);
    float4 o0 = make_float4(
        __uint_as_float(f2tf(lo.x)), __uint_as_float(f2tf(hi.x)),
        __uint_as_float(f2tf(lo.y)), __uint_as_float(f2tf(hi.y)));
    float4 o1 = make_float4(
        __uint_as_float(f2tf(lo.z)), __uint_as_float(f2tf(hi.z)),
        __uint_as_float(f2tf(lo.w)), __uint_as_float(f2tf(hi.w)));
    *reinterpret_cast<float4*>(out + base)     = o0;
    *reinterpret_cast<float4*>(out + base + 4) = o1;
}

// ======================= FFT conv path (fp32, unchanged) ====================
__device__ __forceinline__ float2 cadd(float2 a, float2 b) { return make_float2(a.x + b.x, a.y + b.y); }
__device__ __forceinline__ float2 csub(float2 a, float2 b) { return make_float2(a.x - b.x, a.y - b.y); }
__device__ __forceinline__ float2 cmul(float2 a, float2 b) {
    return make_float2(fmaf(a.x, b.x, -a.y * b.y), fmaf(a.x, b.y, a.y * b.x));
}

#define SWZ(e) ((e) ^ (((e) >> 4) & 7))

template <bool PAD>
__device__ float2* fft4_r8(float2* x, float2* y, const float2* __restrict__ tw, int tid) {
    const float RS2 = 0.70710678118654752f;
    #pragma unroll 1
    for (int st = 0; st < 4; ++st) {
        const int s  = 1 << (3 * st);
        const int i  = tid;
        const int ps = i & ~(s - 1);
        float2 a0, a1, a2, a3, b0, b1, b2, b3;
        {
            float2 x0 = x[SWZ(i)],        x1 = x[SWZ(i + 1024)];
            float2 x2 = x[SWZ(i + 2048)], x3 = x[SWZ(i + 3072)];
            if (PAD && st == 0) {
                a0 = x0; b0 = x0; a1 = x1; b1 = x1;
                a2 = x2; b2 = x2; a3 = x3; b3 = x3;
            } else {
                float2 x4 = x[SWZ(i + 4096)], x5 = x[SWZ(i + 5120)];
                float2 x6 = x[SWZ(i + 6144)], x7 = x[SWZ(i + 7168)];
                a0 = cadd(x0, x4); b0 = csub(x0, x4);
                a1 = cadd(x1, x5); b1 = csub(x1, x5);
                a2 = cadd(x2, x6); b2 = csub(x2, x6);
                a3 = cadd(x3, x7); b3 = csub(x3, x7);
            }
        }
        float2 t0 = cadd(a0, a2), t1 = csub(a0, a2);
        float2 t2 = cadd(a1, a3), t3 = csub(a1, a3);
        float2 e0 = cadd(t0, t2);
        float2 e1 = make_float2(t1.x + t3.y, t1.y - t3.x);
        float2 e2 = csub(t0, t2);
        float2 e3 = make_float2(t1.x - t3.y, t1.y + t3.x);
        float2 c0 = b0;
        float2 c1 = make_float2((b1.x + b1.y) * RS2, (b1.y - b1.x) * RS2);
        float2 c2 = make_float2(b2.y, -b2.x);
        float2 c3 = make_float2((b3.y - b3.x) * RS2, -(b3.x + b3.y) * RS2);
        float2 u0 = cadd(c0, c2), u1 = csub(c0, c2);
        float2 u2 = cadd(c1, c3), u3 = csub(c1, c3);
        float2 o0 = cadd(u0, u2);
        float2 o1 = make_float2(u1.x + u3.y, u1.y - u3.x);
        float2 o2 = csub(u0, u2);
        float2 o3 = make_float2(u1.x - u3.y, u1.y + u3.x);
        float2 w1, w2, w3, w4, w5, w6, w7;
        if (st == 0) {
            w1 = tw[i];
            w2 = cmul(w1, w1); w3 = cmul(w2, w1); w4 = cmul(w2, w2);
            w5 = cmul(w3, w2); w6 = cmul(w3, w3); w7 = cmul(w4, w3);
        } else {
            w1 = tw[ps];     w2 = tw[2 * ps]; w3 = tw[3 * ps]; w4 = tw[4 * ps];
            w5 = tw[5 * ps]; w6 = tw[6 * ps]; w7 = tw[7 * ps];
        }
        const int o = i + 7 * ps;
        y[SWZ(o)]         = e0;
        y[SWZ(o +     s)] = cmul(w1, o0);
        y[SWZ(o + 2 * s)] = cmul(w2, e1);
        y[SWZ(o + 3 * s)] = cmul(w3, o1);
        y[SWZ(o + 4 * s)] = cmul(w4, e2);
        y[SWZ(o + 5 * s)] = cmul(w5, o2);
        y[SWZ(o + 6 * s)] = cmul(w6, e3);
        y[SWZ(o + 7 * s)] = cmul(w7, o3);
        __syncthreads();
        float2* t = x; x = y; y = t;
    }
    return x;
}

__device__ __forceinline__ void r2pair(const float2* __restrict__ P, int k,
                                       float2& zk, float2& zm) {
    if (k == 0) {
        float2 p0 = P[SWZ(0)], p4 = P[SWZ(4096)];
        zk = cadd(p0, p4); zm = zk;
    } else if (k == 4096) {
        float2 p0 = P[SWZ(0)], p4 = P[SWZ(4096)];
        zk = csub(p0, p4); zm = zk;
    } else {
        zk = cadd(P[SWZ(k)],        P[SWZ(k + 4096)]);
        zm = csub(P[SWZ(4096 - k)], P[SWZ(8192 - k)]);
    }
}

__global__ void twiddle_kernel(float2* __restrict__ tw) {
    int k = blockIdx.x * blockDim.x + threadIdx.x;
    if (k < NFFT) {
        float s, c;
        sincospif((float)k / 4096.0f, &s, &c);
        tw[k] = make_float2(c, -s);
    }
}

#define SMEM_FFT ((16384 + 8192) * (int)sizeof(float2))   // 196608 B

__global__ void __launch_bounds__(1024, 1) filter_kernel(
    const float* __restrict__ hfilt, const float2* __restrict__ gtw,
    float2* __restrict__ Hf) {
    extern __shared__ float2 smf[];
    float2* buf0 = smf;
    float2* buf1 = smf + 8192;
    float2* tw   = smf + 16384;
    const int tid = threadIdx.x;
    const int d0  = blockIdx.x * 2;

    {
        const float4* src = reinterpret_cast<const float4*>(gtw);
        float4* dst = reinterpret_cast<float4*>(tw);
        dst[tid]        = src[tid];
        dst[tid + 1024] = src[tid + 1024];
        dst[tid + 2048] = src[tid + 2048];
        dst[tid + 3072] = src[tid + 3072];
    }
    for (int l = tid; l < 4096; l += 1024) {
        float dec = expf(-0.01f * (float)l);
        float2 h = *reinterpret_cast<const float2*>(hfilt + (size_t)l * D_DIM + d0);
        buf0[SWZ(l)] = make_float2(h.x * dec, h.y * dec);
    }
    __syncthreads();
    float2* P = fft4_r8<true>(buf0, buf1, tw, tid);

    float2* H0 = Hf + (size_t)d0 * NFFT;
    float2* H1 = H0 + NFFT;
    for (int k = tid; k <= 4096; k += 1024) {
        float2 zk, zm;
        r2pair(P, k, zk, zm);
        H0[k] = make_float2(0.5f * (zk.x + zm.x), 0.5f * (zk.y - zm.y));
        H1[k] = make_float2(0.5f * (zk.y + zm.y), 0.5f * (zm.x - zk.x));
    }
}

__global__ void __launch_bounds__(1024, 1) conv_kernel(
    const float* __restrict__ vT, const float* __restrict__ uT,
    const float2* __restrict__ Hf, const float2* __restrict__ gtw,
    float* __restrict__ yT) {
    extern __shared__ float2 smf[];
    float2* buf0 = smf;
    float2* buf1 = smf + 8192;
    float2* tw   = smf + 16384;
    const int tid = threadIdx.x;
    const int b   = blockIdx.x >> 9;
    const int d0  = (blockIdx.x & 511) * 2;
    const size_t row = ((size_t)b * D_DIM + d0) * L_DIM;

    {
        const float4* src = reinterpret_cast<const float4*>(gtw);
        float4* dst = reinterpret_cast<float4*>(tw);
        dst[tid]        = src[tid];
        dst[tid + 1024] = src[tid + 1024];
        dst[tid + 2048] = src[tid + 2048];
        dst[tid + 3072] = src[tid + 3072];
    }
    {
        const float4 a  = reinterpret_cast<const float4*>(vT + row)[tid];
        const float4 bq = reinterpret_cast<const float4*>(vT + row + L_DIM)[tid];
        const int l = 4 * tid;
        buf0[SWZ(l + 0)] = make_float2(a.x, bq.x);
        buf0[SWZ(l + 1)] = make_float2(a.y, bq.y);
        buf0[SWZ(l + 2)] = make_float2(a.z, bq.z);
        buf0[SWZ(l + 3)] = make_float2(a.w, bq.w);
    }
    __syncthreads();

    float2* P = fft4_r8<true>(buf0, buf1, tw, tid);
    float2* Q = (P == buf0) ? buf1 : buf0;

    const float2* H0 = Hf + (size_t)d0 * NFFT;
    const float2* H1 = H0 + NFFT;
    for (int k = tid; k <= 4096; k += 1024) {
        const int km = (NFFT - k) & (NFFT - 1);
        float2 zk, zm;
        r2pair(P, k, zk, zm);
        float2 vv0 = make_float2(0.5f * (zk.x + zm.x), 0.5f * (zk.y - zm.y));
        float2 vv1 = make_float2(0.5f * (zk.y + zm.y), 0.5f * (zm.x - zk.x));
        float2 Pc = cmul(vv0, __ldg(H0 + k));
        float2 Qc = cmul(vv1, __ldg(H1 + k));
        Q[SWZ(k)]  = make_float2(Pc.x - Qc.y, -(Pc.y + Qc.x));
        Q[SWZ(km)] = make_float2(Pc.x + Qc.y,  (Pc.y - Qc.x));
    }
    __syncthreads();

    const float4 u0v = __ldg(reinterpret_cast<const float4*>(uT + row) + tid);
    const float4 u1v = __ldg(reinterpret_cast<const float4*>(uT + row + L_DIM) + tid);

    float2* R = fft4_r8<false>(Q, P, tw, tid);

    const float inv = 1.0f / (float)NFFT;
    const int l = 4 * tid;
    float4 y0v, y1v;
    {
        float2 R0 = cadd(R[SWZ(l + 0)], R[SWZ(l + 4096)]);
        float2 R1 = cadd(R[SWZ(l + 1)], R[SWZ(l + 4097)]);
        float2 R2 = cadd(R[SWZ(l + 2)], R[SWZ(l + 4098)]);
        float2 R3 = cadd(R[SWZ(l + 3)], R[SWZ(l + 4099)]);
        y0v.x = __uint_as_float(f2tf( R0.x * inv * u0v.x));
        y0v.y = __uint_as_float(f2tf( R1.x * inv * u0v.y));
        y0v.z = __uint_as_float(f2tf( R2.x * inv * u0v.z));
        y0v.w = __uint_as_float(f2tf( R3.x * inv * u0v.w));
        y1v.x = __uint_as_float(f2tf(-R0.y * inv * u1v.x));
        y1v.y = __uint_as_float(f2tf(-R1.y * inv * u1v.y));
        y1v.z = __uint_as_float(f2tf(-R2.y * inv * u1v.z));
        y1v.w = __uint_as_float(f2tf(-R3.y * inv * u1v.w));
    }
    reinterpret_cast<float4*>(yT + row)[tid]         = y0v;
    reinterpret_cast<float4*>(yT + row + L_DIM)[tid] = y1v;
}

// ======================= launch =============================================
extern "C" void kernel_launch(void* const* d_in, const int* in_sizes, int n_in,
                              void* d_out, int out_size) {
    const float* x   = (const float*)d_in[0];
    const float* Wu  = (const float*)d_in[1];
    const float* bu  = (const float*)d_in[2];
    const float* Wv  = (const float*)d_in[3];
    const float* bv  = (const float*)d_in[4];
    const float* hfl = (const float*)d_in[5];
    const float* Wo  = (const float*)d_in[6];
    const float* bo  = (const float*)d_in[7];
    float* out = (float*)d_out;

    void *pU, *pV, *pX, *pW, *pH, *pT;
    cudaGetSymbolAddress(&pU, g_uT);
    cudaGetSymbolAddress(&pV, g_vT);
    cudaGetSymbolAddress(&pX, g_xr);
    cudaGetSymbolAddress(&pW, g_Wt);
    cudaGetSymbolAddress(&pH, g_Hf);
    cudaGetSymbolAddress(&pT, g_tw);
    float* Wt = (float*)pW;

    cudaFuncSetAttribute(filter_kernel, cudaFuncAttributeMaxDynamicSharedMemorySize, SMEM_FFT);
    cudaFuncSetAttribute(conv_kernel,   cudaFuncAttributeMaxDynamicSharedMemorySize, SMEM_FFT);
    cudaFuncSetAttribute(gemm_uv,  cudaFuncAttributeMaxDynamicSharedMemorySize, UV_SMEM_B);
    cudaFuncSetAttribute(gemm_out, cudaFuncAttributeMaxDynamicSharedMemorySize, OUT_SMEM_B);

    dim3 tb(32, 8);
    twiddle_kernel<<<32, 256>>>((float2*)pT);                                   // 0
    transpose3_k<<<dim3(32, 32, 3), tb>>>(Wu, Wv, Wo, Wt);                      // 1
    round_tf32_k<<<8192, 256>>>(x, (float*)pX);                                 // 2
    gemm_uv<<<dim3(256, 8), 256, UV_SMEM_B>>>(                                  // 3 <- profiled
        Wt, (const float*)pX, bu, bv, (float*)pU, (float*)pV);
    filter_kernel<<<D_DIM / 2, 1024, SMEM_FFT>>>(                               // 4
        hfl, (const float2*)pT, (float2*)pH);
    conv_kernel<<<B_DIM * D_DIM / 2, 1024, SMEM_FFT>>>(                         // 5
        (const float*)pV, (const float*)pU, (const float2*)pH, (const float2*)pT, (float*)pV);
    gemm_out<<<dim3(8, 128), 256, OUT_SMEM_B>>>(                                // 6
        (const float*)pV, Wt + 2 * 1024 * 1024, bo, out);
}

// round 16
// speedup vs baseline: 1.1223x; 1.1223x over previous
#include <cuda_runtime.h>
#include <math.h>
#include <cstdint>

#define B_DIM 4
#define L_DIM 4096
#define D_DIM 1024
#define NFFT 8192

// ---------------- scratch (static device globals; no allocation) -----------
__device__ float  g_uT[(size_t)B_DIM * D_DIM * L_DIM];   // [B, D, L]
__device__ float  g_vT[(size_t)B_DIM * D_DIM * L_DIM];   // [B, D, L] (reused for yT)
__device__ float  g_xr[(size_t)B_DIM * L_DIM * D_DIM];   // x rounded to tf32
__device__ float  g_Wt[(size_t)3 * D_DIM * D_DIM];       // Wu^T, Wv^T, Wo^T (tf32-rounded)
__device__ float2 g_Hf[(size_t)D_DIM * NFFT];            // [D][k<=4096] used
__device__ float2 g_tw[NFFT];                            // exp(-2pi i k / 8192)

// ======================= portable PTX helpers ===============================
__device__ __forceinline__ uint32_t smem_u32(const void* p) {
    uint32_t a;
    asm("{ .reg .u64 t; cvta.to.shared.u64 t, %1; cvt.u32.u64 %0, t; }" : "=r"(a) : "l"(p));
    return a;
}
__device__ __forceinline__ uint32_t f2tf(float f) {
    uint32_t u; asm("cvt.rna.tf32.f32 %0, %1;" : "=r"(u) : "f"(f)); return u;
}
__device__ __forceinline__ void cp_async16(uint32_t saddr, const void* g) {
    asm volatile("cp.async.cg.shared.global [%0], [%1], 16;" :: "r"(saddr), "l"(g));
}
#define CP_COMMIT() asm volatile("cp.async.commit_group;" ::: "memory")
#define CP_WAIT1()  asm volatile("cp.async.wait_group 1;" ::: "memory")
#define CP_WAIT0()  asm volatile("cp.async.wait_group 0;" ::: "memory")

__device__ __forceinline__ void mma_tf32(float* c,
    uint32_t a0, uint32_t a1, uint32_t a2, uint32_t a3, uint32_t b0, uint32_t b1) {
    asm volatile(
        "mma.sync.aligned.m16n8k8.row.col.f32.tf32.tf32.f32 "
        "{%0,%1,%2,%3}, {%4,%5,%6,%7}, {%8,%9}, {%0,%1,%2,%3};"
        : "+f"(c[0]), "+f"(c[1]), "+f"(c[2]), "+f"(c[3])
        : "r"(a0), "r"(a1), "r"(a2), "r"(a3), "r"(b0), "r"(b1));
}
__device__ __forceinline__ uint32_t u32f(float f) { return __float_as_uint(f); }

// ======================= tf32 mma.sync GEMMs (round-13 best) ================
#define AROW2 136
#define UV_STAGE_B   32768
#define UV_SMEM_B    98304
#define OUT_STAGE_B  33792
#define OUT_SMEM_B   101376

// ---- GEMM1 fused u+v: C[i=e][j=m]; z = bx&1 picks (Wu,bu,U) / (Wv,bv,V) ----
__global__ void __launch_bounds__(256, 2) gemm_uv(
    const float* __restrict__ Wt, const float* __restrict__ X,
    const float* __restrict__ bu, const float* __restrict__ bv,
    float* __restrict__ U, float* __restrict__ V)
{
    extern __shared__ float sm[];
    const uint32_t smb = smem_u32(sm);

    const int z  = blockIdx.x & 1;
    const int j0 = (blockIdx.x >> 1) * 128;
    const int i0 = blockIdx.y * 128;
    const float* Ag   = Wt + (size_t)z * 1024 * 1024;
    const float* bias = z ? bv : bu;
    float*       Cg   = z ? V : U;

    const int tid  = threadIdx.x;
    const int lane = tid & 31;
    const int wid  = tid >> 5;
    const int g    = lane >> 2;
    const int fi   = lane & 3;
    const int wm   = (wid & 3) * 32;
    const int wn   = (wid >> 2) * 64;

    const int q     = tid & 7;
    const int rbase = tid >> 3;
    const int qsw   = ((q ^ (rbase & 7)) << 2);

    const float* ag = Ag + (size_t)(i0 + rbase) * 1024 + q * 4;
    const float* bg = X  + (size_t)(j0 + rbase) * 1024 + q * 4;
    const uint32_t soff = (uint32_t)((rbase * 32 + qsw) << 2);

    auto load_stage = [&](int s, uint32_t stoff) {
        const int k0 = s * 32;
        const uint32_t sa  = smb + stoff + soff;
        const uint32_t sbx = smb + stoff + 16384u + soff;
        #pragma unroll
        for (int it = 0; it < 4; ++it) {
            cp_async16(sa  + it * 4096u, ag + (size_t)it * 32 * 1024 + k0);
            cp_async16(sbx + it * 4096u, bg + (size_t)it * 32 * 1024 + k0);
        }
    };

    float c[2][8][4];
    #pragma unroll
    for (int mt = 0; mt < 2; ++mt)
        #pragma unroll
        for (int nt = 0; nt < 8; ++nt)
            #pragma unroll
            for (int r = 0; r < 4; ++r) c[mt][nt][r] = 0.f;

    uint32_t st_cur = 0, st_nxt = UV_STAGE_B, st_spr = 2 * UV_STAGE_B;
    load_stage(0, st_cur); CP_COMMIT();
    load_stage(1, st_nxt); CP_COMMIT();

    int ca0[4], ca1[4];
    #pragma unroll
    for (int kk = 0; kk < 4; ++kk) {
        ca0[kk] = (((2 * kk    ) ^ g) << 2) + fi;
        ca1[kk] = (((2 * kk + 1) ^ g) << 2) + fi;
    }

    #pragma unroll 1
    for (int s = 0; s < 32; ++s) {
        if (s < 31) { CP_WAIT1(); } else { CP_WAIT0(); }
        __syncthreads();
        if (s + 2 < 32) { load_stage(s + 2, st_spr); CP_COMMIT(); }
        const float* A = sm + (st_cur >> 2);
        const float* B = A + 4096;
        #pragma unroll
        for (int kk = 0; kk < 4; ++kk) {
            uint32_t a[2][4];
            #pragma unroll
            for (int mt = 0; mt < 2; ++mt) {
                const int r = wm + mt * 16;
                a[mt][0] = u32f(A[(r + g    ) * 32 + ca0[kk]]);
                a[mt][1] = u32f(A[(r + g + 8) * 32 + ca0[kk]]);
                a[mt][2] = u32f(A[(r + g    ) * 32 + ca1[kk]]);
                a[mt][3] = u32f(A[(r + g + 8) * 32 + ca1[kk]]);
            }
            #pragma unroll
            for (int nt = 0; nt < 8; ++nt) {
                const int n = wn + nt * 8;
                uint32_t b0 = u32f(B[(n + g) * 32 + ca0[kk]]);
                uint32_t b1 = u32f(B[(n + g) * 32 + ca1[kk]]);
                mma_tf32(c[0][nt], a[0][0], a[0][1], a[0][2], a[0][3], b0, b1);
                mma_tf32(c[1][nt], a[1][0], a[1][1], a[1][2], a[1][3], b0, b1);
            }
        }
        const uint32_t t = st_cur; st_cur = st_nxt; st_nxt = st_spr; st_spr = t;
    }

    float* Cs = sm;
    __syncthreads();
    #pragma unroll
    for (int mt = 0; mt < 2; ++mt) {
        #pragma unroll
        for (int nt = 0; nt < 8; ++nt) {
            const int r  = wm + mt * 16 + g;
            const int cc = wn + nt * 8 + 2 * fi;
            *reinterpret_cast<float2*>(&Cs[(size_t)r * 136 + cc]) =
                make_float2(c[mt][nt][0], c[mt][nt][1]);
            *reinterpret_cast<float2*>(&Cs[(size_t)(r + 8) * 136 + cc]) =
                make_float2(c[mt][nt][2], c[mt][nt][3]);
        }
    }
    __syncthreads();

    #pragma unroll 1
    for (int p = 0; p < 16; ++p) {
        const int idx = p * 256 + tid;
        const int row = idx >> 5;
        const int qq  = idx & 31;
        float4 v = *reinterpret_cast<const float4*>(&Cs[(size_t)row * 136 + qq * 4]);
        const float be = __ldg(bias + i0 + row);
        v.x += be; v.y += be; v.z += be; v.w += be;
        const size_t base = ((size_t)(j0 >> 12) << 22) +
                            (size_t)(i0 + row) * 4096 + (j0 & 4095);
        *reinterpret_cast<float4*>(Cg + base + qq * 4) = v;
    }
}

// ---- GEMM2: C[i=m][j=e], A = yT (32x136 padded transposed tile) ------------
__global__ void __launch_bounds__(256, 2) gemm_out(
    const float* __restrict__ Ag, const float* __restrict__ Bg,
    const float* __restrict__ bias, float* __restrict__ Cg)
{
    extern __shared__ float sm[];
    const uint32_t smb = smem_u32(sm);

    const int tid  = threadIdx.x;
    const int lane = tid & 31;
    const int wid  = tid >> 5;
    const int g    = lane >> 2;
    const int fi   = lane & 3;
    const int wm   = (wid & 3) * 32;
    const int wn   = (wid >> 2) * 64;
    const int i0   = blockIdx.y * 128;
    const int j0   = blockIdx.x * 128;

    const int q     = tid & 7;
    const int rbase = tid >> 3;
    const int qsw   = ((q ^ (rbase & 7)) << 2);

    const float* bg = Bg + (size_t)(j0 + rbase) * 1024 + q * 4;
    const uint32_t soffB = (uint32_t)((rbase * 32 + qsw) << 2);

    const int bb = i0 >> 12, l0 = i0 & 4095;
    const int arow = tid >> 5;
    const int aq   = tid & 31;
    const float* ag = Ag + ((size_t)bb * 1024) * 4096 + l0 + aq * 4;
    const uint32_t soffA = (uint32_t)((arow * AROW2 + aq * 4) << 2);

    auto load_stage = [&](int s, uint32_t stoff) {
        const int k0 = s * 32;
        const uint32_t sa  = smb + stoff + soffA;
        const uint32_t sbx = smb + stoff + 17408u + soffB;
        #pragma unroll
        for (int it = 0; it < 4; ++it)
            cp_async16(sa + it * (8 * AROW2 * 4),
                       ag + (size_t)(k0 + arow + it * 8) * 4096);
        #pragma unroll
        for (int it = 0; it < 4; ++it)
            cp_async16(sbx + it * 4096u, bg + (size_t)it * 32 * 1024 + k0);
    };

    float c[2][8][4];
    #pragma unroll
    for (int mt = 0; mt < 2; ++mt)
        #pragma unroll
        for (int nt = 0; nt < 8; ++nt)
            #pragma unroll
            for (int r = 0; r < 4; ++r) c[mt][nt][r] = 0.f;

    uint32_t st_cur = 0, st_nxt = OUT_STAGE_B, st_spr = 2 * OUT_STAGE_B;
    load_stage(0, st_cur); CP_COMMIT();
    load_stage(1, st_nxt); CP_COMMIT();

    int cb0[4], cb1[4];
    #pragma unroll
    for (int kk = 0; kk < 4; ++kk) {
        cb0[kk] = (((2 * kk    ) ^ g) << 2) + fi;
        cb1[kk] = (((2 * kk + 1) ^ g) << 2) + fi;
    }

    #pragma unroll 1
    for (int s = 0; s < 32; ++s) {
        if (s < 31) { CP_WAIT1(); } else { CP_WAIT0(); }
        __syncthreads();
        if (s + 2 < 32) { load_stage(s + 2, st_spr); CP_COMMIT(); }
        const float* A = sm + (st_cur >> 2);
        const float* B = A + 4352;
        #pragma unroll
        for (int kk = 0; kk < 4; ++kk) {
            const int k0 = kk * 8;
            uint32_t a[2][4];
            #pragma unroll
            for (int mt = 0; mt < 2; ++mt) {
                const int r = wm + mt * 16;
                a[mt][0] = u32f(A[(k0 + fi    ) * AROW2 + r + g    ]);
                a[mt][1] = u32f(A[(k0 + fi    ) * AROW2 + r + g + 8]);
                a[mt][2] = u32f(A[(k0 + fi + 4) * AROW2 + r + g    ]);
                a[mt][3] = u32f(A[(k0 + fi + 4) * AROW2 + r + g + 8]);
            }
            #pragma unroll
            for (int nt = 0; nt < 8; ++nt) {
                const int n = wn + nt * 8;
                uint32_t b0 = u32f(B[(n + g) * 32 + cb0[kk]]);
                uint32_t b1 = u32f(B[(n + g) * 32 + cb1[kk]]);
                mma_tf32(c[0][nt], a[0][0], a[0][1], a[0][2], a[0][3], b0, b1);
                mma_tf32(c[1][nt], a[1][0], a[1][1], a[1][2], a[1][3], b0, b1);
            }
        }
        const uint32_t t = st_cur; st_cur = st_nxt; st_nxt = st_spr; st_spr = t;
    }

    float* Cs = sm;
    __syncthreads();
    #pragma unroll
    for (int mt = 0; mt < 2; ++mt) {
        #pragma unroll
        for (int nt = 0; nt < 8; ++nt) {
            const int r  = wm + mt * 16 + g;
            const int cc = wn + nt * 8 + 2 * fi;
            *reinterpret_cast<float2*>(&Cs[(size_t)r * 136 + cc]) =
                make_float2(c[mt][nt][0], c[mt][nt][1]);
            *reinterpret_cast<float2*>(&Cs[(size_t)(r + 8) * 136 + cc]) =
                make_float2(c[mt][nt][2], c[mt][nt][3]);
        }
    }
    __syncthreads();

    #pragma unroll 1
    for (int p = 0; p < 16; ++p) {
        const int idx = p * 256 + tid;
        const int row = idx >> 5;
        const int qq  = idx & 31;
        float4 v = *reinterpret_cast<const float4*>(&Cs[(size_t)row * 136 + qq * 4]);
        float4 bz = *reinterpret_cast<const float4*>(bias + j0 + qq * 4);
        v.x += bz.x; v.y += bz.y; v.z += bz.z; v.w += bz.w;
        *reinterpret_cast<float4*>(Cg + (size_t)(i0 + row) * 1024 + j0 + qq * 4) = v;
    }
}

// ---------------- fused 3x weight transpose + tf32 rounding ------------------
__global__ void transpose3_k(const float* __restrict__ W0, const float* __restrict__ W1,
                             const float* __restrict__ W2, float* __restrict__ out) {
    __shared__ float t[32][33];
    const float* in = (blockIdx.z == 0) ? W0 : ((blockIdx.z == 1) ? W1 : W2);
    float* o = out + (size_t)blockIdx.z * 1024 * 1024;
    const int r0 = blockIdx.y * 32;
    const int c0 = blockIdx.x * 32;
    #pragma unroll
    for (int i = threadIdx.y; i < 32; i += 8)
        t[i][threadIdx.x] = in[(size_t)(r0 + i) * 1024 + c0 + threadIdx.x];
    __syncthreads();
    #pragma unroll
    for (int i = threadIdx.y; i < 32; i += 8)
        o[(size_t)(c0 + i) * 1024 + r0 + threadIdx.x] =
            __uint_as_float(f2tf(t[threadIdx.x][i]));
}

__global__ void round_tf32_k(const float* __restrict__ in, float* __restrict__ out) {
    const size_t i = ((size_t)blockIdx.x * 256 + threadIdx.x) * 4;
    float4 v = *reinterpret_cast<const float4*>(in + i);
    v.x = __uint_as_float(f2tf(v.x));
    v.y = __uint_as_float(f2tf(v.y));
    v.z = __uint_as_float(f2tf(v.z));
    v.w = __uint_as_float(f2tf(v.w));
    *reinterpret_cast<float4*>(out + i) = v;
}

// ======================= FFT conv path (fp32) ===============================
__device__ __forceinline__ float2 cadd(float2 a, float2 b) { return make_float2(a.x + b.x, a.y + b.y); }
__device__ __forceinline__ float2 csub(float2 a, float2 b) { return make_float2(a.x - b.x, a.y - b.y); }
__device__ __forceinline__ float2 cmul(float2 a, float2 b) {
    return make_float2(fmaf(a.x, b.x, -a.y * b.y), fmaf(a.x, b.y, a.y * b.x));
}

#define SWZ(e) ((e) ^ (((e) >> 4) & 7))

// 4 radix-8 Stockham stages, s = 1,8,64,512. No final radix-2 (callers fuse it).
// PAD: input known zero in [4096, 8192) (skips those loads in stage 0).
// tw: GLOBAL twiddle table (L1/L2-resident; stage-0 coalesced, rest broadcast).
template <bool PAD>
__device__ float2* fft4_r8(float2* x, float2* y, const float2* __restrict__ tw, int tid) {
    const float RS2 = 0.70710678118654752f;
    #pragma unroll 1
    for (int st = 0; st < 4; ++st) {
        const int s  = 1 << (3 * st);
        const int i  = tid;
        const int ps = i & ~(s - 1);
        float2 a0, a1, a2, a3, b0, b1, b2, b3;
        {
            float2 x0 = x[SWZ(i)],        x1 = x[SWZ(i + 1024)];
            float2 x2 = x[SWZ(i + 2048)], x3 = x[SWZ(i + 3072)];
            if (PAD && st == 0) {
                a0 = x0; b0 = x0; a1 = x1; b1 = x1;
                a2 = x2; b2 = x2; a3 = x3; b3 = x3;
            } else {
                float2 x4 = x[SWZ(i + 4096)], x5 = x[SWZ(i + 5120)];
                float2 x6 = x[SWZ(i + 6144)], x7 = x[SWZ(i + 7168)];
                a0 = cadd(x0, x4); b0 = csub(x0, x4);
                a1 = cadd(x1, x5); b1 = csub(x1, x5);
                a2 = cadd(x2, x6); b2 = csub(x2, x6);
                a3 = cadd(x3, x7); b3 = csub(x3, x7);
            }
        }
        float2 t0 = cadd(a0, a2), t1 = csub(a0, a2);
        float2 t2 = cadd(a1, a3), t3 = csub(a1, a3);
        float2 e0 = cadd(t0, t2);
        float2 e1 = make_float2(t1.x + t3.y, t1.y - t3.x);
        float2 e2 = csub(t0, t2);
        float2 e3 = make_float2(t1.x - t3.y, t1.y + t3.x);
        float2 c0 = b0;
        float2 c1 = make_float2((b1.x + b1.y) * RS2, (b1.y - b1.x) * RS2);
        float2 c2 = make_float2(b2.y, -b2.x);
        float2 c3 = make_float2((b3.y - b3.x) * RS2, -(b3.x + b3.y) * RS2);
        float2 u0 = cadd(c0, c2), u1 = csub(c0, c2);
        float2 u2 = cadd(c1, c3), u3 = csub(c1, c3);
        float2 o0 = cadd(u0, u2);
        float2 o1 = make_float2(u1.x + u3.y, u1.y - u3.x);
        float2 o2 = csub(u0, u2);
        float2 o3 = make_float2(u1.x - u3.y, u1.y + u3.x);
        float2 w1, w2, w3, w4, w5, w6, w7;
        if (st == 0) {
            w1 = __ldg(tw + i);
            w2 = cmul(w1, w1); w3 = cmul(w2, w1); w4 = cmul(w2, w2);
            w5 = cmul(w3, w2); w6 = cmul(w3, w3); w7 = cmul(w4, w3);
        } else {
            w1 = __ldg(tw + ps);     w2 = __ldg(tw + 2 * ps);
            w3 = __ldg(tw + 3 * ps); w4 = __ldg(tw + 4 * ps);
            w5 = __ldg(tw + 5 * ps); w6 = __ldg(tw + 6 * ps);
            w7 = __ldg(tw + 7 * ps);
        }
        const int o = i + 7 * ps;
        y[SWZ(o)]         = e0;
        y[SWZ(o +     s)] = cmul(w1, o0);
        y[SWZ(o + 2 * s)] = cmul(w2, e1);
        y[SWZ(o + 3 * s)] = cmul(w3, o1);
        y[SWZ(o + 4 * s)] = cmul(w4, e2);
        y[SWZ(o + 5 * s)] = cmul(w5, o2);
        y[SWZ(o + 6 * s)] = cmul(w6, e3);
        y[SWZ(o + 7 * s)] = cmul(w7, o3);
        __syncthreads();
        float2* t = x; x = y; y = t;
    }
    return x;                                  // 4 swaps -> result in input buf
}

// Z[k], Z[(8192-k)&8191] reconstructed from pre-r2 array P (k in [0, 4096]).
__device__ __forceinline__ void r2pair(const float2* __restrict__ P, int k,
                                       float2& zk, float2& zm) {
    if (k == 0) {
        float2 p0 = P[SWZ(0)], p4 = P[SWZ(4096)];
        zk = cadd(p0, p4); zm = zk;
    } else if (k == 4096) {
        float2 p0 = P[SWZ(0)], p4 = P[SWZ(4096)];
        zk = csub(p0, p4); zm = zk;
    } else {
        zk = cadd(P[SWZ(k)],        P[SWZ(k + 4096)]);
        zm = csub(P[SWZ(4096 - k)], P[SWZ(8192 - k)]);
    }
}

__global__ void twiddle_kernel(float2* __restrict__ tw) {
    int k = blockIdx.x * blockDim.x + threadIdx.x;
    if (k < NFFT) {
        float s, c;
        sincospif((float)k / 4096.0f, &s, &c);
        tw[k] = make_float2(c, -s);
    }
}

#define SMEM_FFT (16384 * (int)sizeof(float2))   // 131072 B (no tw staging)

// ---- packed filter FFT: 2 channels per block; stores Hermitian half --------
__global__ void __launch_bounds__(1024, 1) filter_kernel(
    const float* __restrict__ hfilt, const float2* __restrict__ gtw,
    float2* __restrict__ Hf) {
    extern __shared__ float2 smf[];
    float2* buf0 = smf;
    float2* buf1 = smf + 8192;
    const int tid = threadIdx.x;
    const int d0  = blockIdx.x * 2;

    for (int l = tid; l < 4096; l += 1024) {
        float dec = expf(-0.01f * (float)l);
        float2 h = *reinterpret_cast<const float2*>(hfilt + (size_t)l * D_DIM + d0);
        buf0[SWZ(l)] = make_float2(h.x * dec, h.y * dec);
    }
    __syncthreads();
    float2* P = fft4_r8<true>(buf0, buf1, gtw, tid);   // pre-r2 spectrum

    float2* H0 = Hf + (size_t)d0 * NFFT;
    float2* H1 = H0 + NFFT;
    for (int k = tid; k <= 4096; k += 1024) {
        float2 zk, zm;
        r2pair(P, k, zk, zm);                          // fused final radix-2
        H0[k] = make_float2(0.5f * (zk.x + zm.x), 0.5f * (zk.y - zm.y));
        H1[k] = make_float2(0.5f * (zk.y + zm.y), 0.5f * (zm.x - zk.x));
    }
}

// ---- packed conv + gate: float4 GLOBAL I/O, element-wise SWZ smem indexing -
__global__ void __launch_bounds__(1024, 1) conv_kernel(
    const float* __restrict__ vT, const float* __restrict__ uT,
    const float2* __restrict__ Hf, const float2* __restrict__ gtw,
    float* __restrict__ yT) {
    extern __shared__ float2 smf[];
    float2* buf0 = smf;
    float2* buf1 = smf + 8192;
    const int tid = threadIdx.x;
    const int b   = blockIdx.x >> 9;
    const int d0  = (blockIdx.x & 511) * 2;
    const size_t row = ((size_t)b * D_DIM + d0) * L_DIM;

    {   // float4 global loads; element-wise swizzled smem stores
        const float4 a  = reinterpret_cast<const float4*>(vT + row)[tid];
        const float4 bq = reinterpret_cast<const float4*>(vT + row + L_DIM)[tid];
        const int l = 4 * tid;
        buf0[SWZ(l + 0)] = make_float2(a.x, bq.x);
        buf0[SWZ(l + 1)] = make_float2(a.y, bq.y);
        buf0[SWZ(l + 2)] = make_float2(a.z, bq.z);
        buf0[SWZ(l + 3)] = make_float2(a.w, bq.w);
    }
    __syncthreads();

    float2* P = fft4_r8<true>(buf0, buf1, gtw, tid);   // pre-r2 fwd spectrum
    float2* Q = (P == buf0) ? buf1 : buf0;             // output buffer for conj(Y)

    const float2* H0 = Hf + (size_t)d0 * NFFT;
    const float2* H1 = H0 + NFFT;
    for (int k = tid; k <= 4096; k += 1024) {
        const int km = (NFFT - k) & (NFFT - 1);
        float2 zk, zm;
        r2pair(P, k, zk, zm);                          // fused final radix-2
        float2 vv0 = make_float2(0.5f * (zk.x + zm.x), 0.5f * (zk.y - zm.y));
        float2 vv1 = make_float2(0.5f * (zk.y + zm.y), 0.5f * (zm.x - zk.x));
        float2 Pc = cmul(vv0, __ldg(H0 + k));
        float2 Qc = cmul(vv1, __ldg(H1 + k));
        Q[SWZ(k)]  = make_float2(Pc.x - Qc.y, -(Pc.y + Qc.x));
        Q[SWZ(km)] = make_float2(Pc.x + Qc.y,  (Pc.y - Qc.x));
    }
    __syncthreads();

    // prefetch u into registers: DRAM latency hidden under the inverse FFT
    const float4 u0v = __ldg(reinterpret_cast<const float4*>(uT + row) + tid);
    const float4 u1v = __ldg(reinterpret_cast<const float4*>(uT + row + L_DIM) + tid);

    // inverse FFT (4 radix-8 stages); final radix-2 fused into epilogue combine
    float2* R = fft4_r8<false>(Q, P, gtw, tid);

    const float inv = 1.0f / (float)NFFT;
    const int l = 4 * tid;
    float4 y0v, y1v;
    {
        float2 R0 = cadd(R[SWZ(l + 0)], R[SWZ(l + 4096)]);
        float2 R1 = cadd(R[SWZ(l + 1)], R[SWZ(l + 4097)]);
        float2 R2 = cadd(R[SWZ(l + 2)], R[SWZ(l + 4098)]);
        float2 R3 = cadd(R[SWZ(l + 3)], R[SWZ(l + 4099)]);
        y0v.x = __uint_as_float(f2tf( R0.x * inv * u0v.x));
        y0v.y = __uint_as_float(f2tf( R1.x * inv * u0v.y));
        y0v.z = __uint_as_float(f2tf( R2.x * inv * u0v.z));
        y0v.w = __uint_as_float(f2tf( R3.x * inv * u0v.w));
        y1v.x = __uint_as_float(f2tf(-R0.y * inv * u1v.x));
        y1v.y = __uint_as_float(f2tf(-R1.y * inv * u1v.y));
        y1v.z = __uint_as_float(f2tf(-R2.y * inv * u1v.z));
        y1v.w = __uint_as_float(f2tf(-R3.y * inv * u1v.w));
    }
    reinterpret_cast<float4*>(yT + row)[tid]         = y0v;
    reinterpret_cast<float4*>(yT + row + L_DIM)[tid] = y1v;
}

// ======================= launch =============================================
extern "C" void kernel_launch(void* const* d_in, const int* in_sizes, int n_in,
                              void* d_out, int out_size) {
    const float* x   = (const float*)d_in[0];
    const float* Wu  = (const float*)d_in[1];
    const float* bu  = (const float*)d_in[2];
    const float* Wv  = (const float*)d_in[3];
    const float* bv  = (const float*)d_in[4];
    const float* hfl = (const float*)d_in[5];
    const float* Wo  = (const float*)d_in[6];
    const float* bo  = (const float*)d_in[7];
    float* out = (float*)d_out;

    void *pU, *pV, *pX, *pW, *pH, *pT;
    cudaGetSymbolAddress(&pU, g_uT);
    cudaGetSymbolAddress(&pV, g_vT);
    cudaGetSymbolAddress(&pX, g_xr);
    cudaGetSymbolAddress(&pW, g_Wt);
    cudaGetSymbolAddress(&pH, g_Hf);
    cudaGetSymbolAddress(&pT, g_tw);
    float* Wt = (float*)pW;

    cudaFuncSetAttribute(filter_kernel, cudaFuncAttributeMaxDynamicSharedMemorySize, SMEM_FFT);
    cudaFuncSetAttribute(conv_kernel,   cudaFuncAttributeMaxDynamicSharedMemorySize, SMEM_FFT);
    cudaFuncSetAttribute(gemm_uv,  cudaFuncAttributeMaxDynamicSharedMemorySize, UV_SMEM_B);
    cudaFuncSetAttribute(gemm_out, cudaFuncAttributeMaxDynamicSharedMemorySize, OUT_SMEM_B);

    dim3 tb(32, 8);
    twiddle_kernel<<<32, 256>>>((float2*)pT);                                   // 0
    transpose3_k<<<dim3(32, 32, 3), tb>>>(Wu, Wv, Wo, Wt);                      // 1
    round_tf32_k<<<16384, 256>>>(x, (float*)pX);                                // 2
    gemm_uv<<<dim3(256, 8), 256, UV_SMEM_B>>>(                                  // 3 <- profiled
        Wt, (const float*)pX, bu, bv, (float*)pU, (float*)pV);
    filter_kernel<<<D_DIM / 2, 1024, SMEM_FFT>>>(                               // 4
        hfl, (const float2*)pT, (float2*)pH);
    conv_kernel<<<B_DIM * D_DIM / 2, 1024, SMEM_FFT>>>(                         // 5
        (const float*)pV, (const float*)pU, (const float2*)pH, (const float2*)pT, (float*)pV);
    gemm_out<<<dim3(8, 128), 256, OUT_SMEM_B>>>(                                // 6
        (const float*)pV, Wt + 2 * 1024 * 1024, bo, out);
}